// round 6
// baseline (speedup 1.0000x reference)
#include <cuda_runtime.h>
#include <cuda_bf16.h>
#include <stdint.h>

#define N_NODES 100000
#define N_EDGES 1600000
#define IN_DIM  128
#define HID_DIM 64
#define OUT_DIM 128

// Scratch (allocation-free rule: __device__ globals)
__device__ __align__(16) float g_hs [(size_t)N_NODES * HID_DIM];   // (x@Wc)*dinv[row]
__device__ int g_cnt[N_NODES];
__device__ int g_off[N_NODES];   // per-block exclusive scan of cnt
__device__ int g_pos[N_NODES];
__device__ int g_bsum[128];
__device__ int g_csr[N_EDGES];

// ---------------------------------------------------------------- f32x2 helpers
__device__ __forceinline__ unsigned long long pack2(float x, float y) {
    unsigned long long r;
    asm("mov.b64 %0, {%1,%2};" : "=l"(r) : "f"(x), "f"(y));
    return r;
}
__device__ __forceinline__ float2 unpack2(unsigned long long v) {
    float2 r;
    asm("mov.b64 {%0,%1}, %2;" : "=f"(r.x), "=f"(r.y) : "l"(v));
    return r;
}
__device__ __forceinline__ void ffma2(unsigned long long& d, unsigned long long a,
                                      unsigned long long b) {
    asm("fma.rn.f32x2 %0, %1, %2, %0;" : "+l"(d) : "l"(a), "l"(b));
}
__device__ __forceinline__ unsigned long long mul2(unsigned long long a,
                                                   unsigned long long b) {
    unsigned long long d;
    asm("mul.rn.f32x2 %0, %1, %2;" : "=l"(d) : "l"(a), "l"(b));
    return d;
}
__device__ __forceinline__ unsigned long long add2(unsigned long long a,
                                                   unsigned long long b) {
    unsigned long long d;
    asm("add.rn.f32x2 %0, %1, %2;" : "=l"(d) : "l"(a), "l"(b));
    return d;
}

// ---------------------------------------------------------------- CSR build
__global__ void zero_kernel(int n) {
    int i = blockIdx.x * blockDim.x + threadIdx.x;
    if (i < n) g_cnt[i] = 0;
}

__global__ void cnt_kernel(const int* __restrict__ dst, int e) {
    int i = blockIdx.x * blockDim.x + threadIdx.x;
    if (i < e) atomicAdd(&g_cnt[dst[i]], 1);
}

// exclusive scan, stage 1: per-block (1024) scan + block sums; also zero g_pos
__global__ __launch_bounds__(1024) void scan1_kernel(int n) {
    __shared__ int sh[1024];
    int t = threadIdx.x;
    int i = blockIdx.x * 1024 + t;
    int v = (i < n) ? g_cnt[i] : 0;
    sh[t] = v;
    __syncthreads();
    #pragma unroll
    for (int d = 1; d < 1024; d <<= 1) {
        int u = (t >= d) ? sh[t - d] : 0;
        __syncthreads();
        sh[t] += u;
        __syncthreads();
    }
    if (i < n) { g_off[i] = sh[t] - v; g_pos[i] = 0; }
    if (t == 1023) g_bsum[blockIdx.x] = sh[1023];
}

// stage 2: scan block sums (nb <= 128), one block of 128 threads
__global__ void scan2_kernel(int nb) {
    __shared__ int sh[128];
    int t = threadIdx.x;
    int v = (t < nb) ? g_bsum[t] : 0;
    sh[t] = v;
    __syncthreads();
    #pragma unroll
    for (int d = 1; d < 128; d <<= 1) {
        int u = (t >= d) ? sh[t - d] : 0;
        __syncthreads();
        sh[t] += u;
        __syncthreads();
    }
    if (t < nb) g_bsum[t] = sh[t] - v;
}

// ---------------------------------------------------------------- GEMM1 + fill
// Blocks [0, nGemm): hs[r][c] = rsqrt(cnt[r]+1) * sum_k x[r][k]*Wc[k][c]
//   Tile M=128, N=64, K chunks of 32. 256 thr; warp tc owns 8 cols (broadcast W);
//   lane tr owns rows {tr, tr+32, tr+64, tr+96}.
// Blocks [nGemm, nGemm+nFill): CSR fill (overlaps with the GEMM).
__global__ __launch_bounds__(256) void gemm1_fill_kernel(const float* __restrict__ x,
                                                         const float* __restrict__ Wc,
                                                         const int* __restrict__ src,
                                                         const int* __restrict__ dst,
                                                         int n, int e, int nGemm) {
    __shared__ float4 Xs[128 * 9];
    __shared__ float4 Ws[32 * 16];

    if (blockIdx.x >= nGemm) {   // ---- fill part
        int i = (blockIdx.x - nGemm) * 256 + threadIdx.x;
        if (i < e) {
            int d = dst[i];
            int p = g_off[d] + g_bsum[d >> 10] + atomicAdd(&g_pos[d], 1);
            g_csr[p] = src[i];
        }
        return;
    }

    const int t = threadIdx.x;
    const int rowBase = blockIdx.x * 128;
    const int tr = t & 31;
    const int tc = t >> 5;

    unsigned long long acc[4][4];
    #pragma unroll
    for (int i = 0; i < 4; i++)
        #pragma unroll
        for (int c2 = 0; c2 < 4; c2++) acc[i][c2] = 0ull;

    const float4* Xg = (const float4*)x;
    const float4* Wg = (const float4*)Wc;

    for (int c = 0; c < 4; c++) {
        #pragma unroll
        for (int i = 0; i < 2; i++) {
            int idx = t + i * 256;
            int k = idx >> 4, col4 = idx & 15;
            Ws[idx] = Wg[(c * 32 + k) * 16 + col4];
        }
        #pragma unroll
        for (int i = 0; i < 4; i++) {
            int idx = t + i * 256;
            int r = idx >> 3, q = idx & 7;
            int row = rowBase + r;
            float4 v = make_float4(0.f, 0.f, 0.f, 0.f);
            if (row < n) v = Xg[(size_t)row * 32 + c * 8 + q];
            Xs[r * 9 + q] = v;
        }
        __syncthreads();

        #pragma unroll
        for (int kq = 0; kq < 8; kq++) {
            float4 xv[4];
            #pragma unroll
            for (int i = 0; i < 4; i++) xv[i] = Xs[(tr + 32 * i) * 9 + kq];
            #pragma unroll
            for (int kk = 0; kk < 4; kk++) {
                float4 w0 = Ws[(kq * 4 + kk) * 16 + tc * 2];
                float4 w1 = Ws[(kq * 4 + kk) * 16 + tc * 2 + 1];
                unsigned long long wp0 = pack2(w0.x, w0.y);
                unsigned long long wp1 = pack2(w0.z, w0.w);
                unsigned long long wp2 = pack2(w1.x, w1.y);
                unsigned long long wp3 = pack2(w1.z, w1.w);
                #pragma unroll
                for (int i = 0; i < 4; i++) {
                    float s = (kk == 0) ? xv[i].x : (kk == 1) ? xv[i].y
                            : (kk == 2) ? xv[i].z : xv[i].w;
                    unsigned long long ss = pack2(s, s);
                    ffma2(acc[i][0], ss, wp0);
                    ffma2(acc[i][1], ss, wp1);
                    ffma2(acc[i][2], ss, wp2);
                    ffma2(acc[i][3], ss, wp3);
                }
            }
        }
        __syncthreads();
    }

    #pragma unroll
    for (int i = 0; i < 4; i++) {
        int row = rowBase + tr + 32 * i;
        if (row < n) {
            float dv = rsqrtf((float)g_cnt[row] + 1.0f);
            unsigned long long dd = pack2(dv, dv);
            float2 a = unpack2(mul2(acc[i][0], dd));
            float2 b = unpack2(mul2(acc[i][1], dd));
            float2 cc = unpack2(mul2(acc[i][2], dd));
            float2 d = unpack2(mul2(acc[i][3], dd));
            size_t off = (size_t)row * 16 + tc * 2;
            ((float4*)g_hs)[off]     = make_float4(a.x, a.y, b.x, b.y);
            ((float4*)g_hs)[off + 1] = make_float4(cc.x, cc.y, d.x, d.y);
        }
    }
}

// ---------------------------------------------------------------- agg + GEMM2
// Block handles 64 rows. Phase 1: 16 groups of 16 threads aggregate 4 nodes each
// (self + CSR neighbors), apply dinv/bias/relu, write Hs. Phase 2: out = Hs@Wlin+blin.
__global__ __launch_bounds__(256) void agg_gemm2_kernel(const float* __restrict__ Wlin,
                                                        const float* __restrict__ bconv,
                                                        const float* __restrict__ blin,
                                                        float* __restrict__ out,
                                                        int n) {
    __shared__ float4 Hs[64 * 17];   // 64 rows x 16 float4 (+1 pad)
    __shared__ float4 Ws[32 * 32];   // 32 k x 128 cols
    const int t = threadIdx.x;
    const int rowBase = blockIdx.x * 64;
    const int tr = t & 31;
    const int tc = t >> 5;

    // ---- phase 1: aggregate
    {
        const int grp = t >> 4;      // 0..15
        const int c = t & 15;        // float4 chunk
        const float4* hs4 = (const float4*)g_hs;
        float4 bcv = __ldg((const float4*)&bconv[c * 4]);
        #pragma unroll
        for (int nn = 0; nn < 4; nn++) {
            int r = grp * 4 + nn;
            int node = rowBase + r;
            float4 res = make_float4(0.f, 0.f, 0.f, 0.f);
            if (node < n) {
                float4 a0 = hs4[(size_t)node * 16 + c];   // self-loop (pre-scaled)
                float4 a1 = make_float4(0.f, 0.f, 0.f, 0.f);
                float4 a2 = make_float4(0.f, 0.f, 0.f, 0.f);
                float4 a3 = make_float4(0.f, 0.f, 0.f, 0.f);
                int cnt = g_cnt[node];
                int beg = g_off[node] + g_bsum[node >> 10];
                int end = beg + cnt;
                int j = beg;
                for (; j + 3 < end; j += 4) {
                    int s0 = g_csr[j],     s1 = g_csr[j + 1];
                    int s2 = g_csr[j + 2], s3 = g_csr[j + 3];
                    float4 v0 = hs4[(size_t)s0 * 16 + c];
                    float4 v1 = hs4[(size_t)s1 * 16 + c];
                    float4 v2 = hs4[(size_t)s2 * 16 + c];
                    float4 v3 = hs4[(size_t)s3 * 16 + c];
                    a0.x += v0.x; a0.y += v0.y; a0.z += v0.z; a0.w += v0.w;
                    a1.x += v1.x; a1.y += v1.y; a1.z += v1.z; a1.w += v1.w;
                    a2.x += v2.x; a2.y += v2.y; a2.z += v2.z; a2.w += v2.w;
                    a3.x += v3.x; a3.y += v3.y; a3.z += v3.z; a3.w += v3.w;
                }
                for (; j < end; j++) {
                    int s0 = g_csr[j];
                    float4 v0 = hs4[(size_t)s0 * 16 + c];
                    a0.x += v0.x; a0.y += v0.y; a0.z += v0.z; a0.w += v0.w;
                }
                a0.x += a1.x + a2.x + a3.x;
                a0.y += a1.y + a2.y + a3.y;
                a0.z += a1.z + a2.z + a3.z;
                a0.w += a1.w + a2.w + a3.w;
                float dv = rsqrtf((float)cnt + 1.0f);
                res.x = fmaxf(fmaf(a0.x, dv, bcv.x), 0.f);
                res.y = fmaxf(fmaf(a0.y, dv, bcv.y), 0.f);
                res.z = fmaxf(fmaf(a0.z, dv, bcv.z), 0.f);
                res.w = fmaxf(fmaf(a0.w, dv, bcv.w), 0.f);
            }
            Hs[r * 17 + c] = res;
        }
    }

    // ---- phase 2: GEMM, K=64 in 2 chunks of 32 (Ws reuse)
    unsigned long long acc[2][8];
    #pragma unroll
    for (int i = 0; i < 2; i++)
        #pragma unroll
        for (int c2 = 0; c2 < 8; c2++) acc[i][c2] = 0ull;

    const float4* Wg = (const float4*)Wlin;

    for (int c = 0; c < 2; c++) {
        __syncthreads();   // Hs ready (c==0) / Ws drained (c==1)
        #pragma unroll
        for (int i = 0; i < 4; i++) {
            int idx = t + i * 256;
            int k = idx >> 5, col4 = idx & 31;
            Ws[idx] = Wg[(c * 32 + k) * 32 + col4];
        }
        __syncthreads();

        #pragma unroll
        for (int kq = 0; kq < 8; kq++) {
            float4 xv[2];
            #pragma unroll
            for (int i = 0; i < 2; i++) xv[i] = Hs[(tr + 32 * i) * 17 + c * 8 + kq];
            #pragma unroll
            for (int kk = 0; kk < 4; kk++) {
                unsigned long long wp[8];
                #pragma unroll
                for (int m = 0; m < 4; m++) {
                    float4 w = Ws[(kq * 4 + kk) * 32 + tc * 4 + m];
                    wp[m * 2]     = pack2(w.x, w.y);
                    wp[m * 2 + 1] = pack2(w.z, w.w);
                }
                #pragma unroll
                for (int i = 0; i < 2; i++) {
                    float s = (kk == 0) ? xv[i].x : (kk == 1) ? xv[i].y
                            : (kk == 2) ? xv[i].z : xv[i].w;
                    unsigned long long ss = pack2(s, s);
                    #pragma unroll
                    for (int c2 = 0; c2 < 8; c2++) ffma2(acc[i][c2], ss, wp[c2]);
                }
            }
        }
    }

    unsigned long long blp[8];
    #pragma unroll
    for (int m = 0; m < 4; m++) {
        float4 b = __ldg((const float4*)&blin[tc * 16 + m * 4]);
        blp[m * 2]     = pack2(b.x, b.y);
        blp[m * 2 + 1] = pack2(b.z, b.w);
    }
    #pragma unroll
    for (int i = 0; i < 2; i++) {
        int row = rowBase + tr + 32 * i;
        if (row < n) {
            size_t off = (size_t)row * 32 + tc * 4;
            #pragma unroll
            for (int m = 0; m < 4; m++) {
                float2 lo = unpack2(add2(acc[i][m * 2],     blp[m * 2]));
                float2 hi = unpack2(add2(acc[i][m * 2 + 1], blp[m * 2 + 1]));
                ((float4*)out)[off + m] = make_float4(lo.x, lo.y, hi.x, hi.y);
            }
        }
    }
}

// ---------------------------------------------------------------- launch
extern "C" void kernel_launch(void* const* d_in, const int* in_sizes, int n_in,
                              void* d_out, int out_size) {
    const float* x  = (const float*)d_in[0];
    const int*   ei = (const int*)  d_in[1];
    const float* Wc = (const float*)d_in[2];
    const float* bc = (const float*)d_in[3];
    const float* Wl = (const float*)d_in[4];
    const float* bl = (const float*)d_in[5];
    float*       out = (float*)d_out;

    const int n = in_sizes[0] / IN_DIM;      // 100000
    const int e = in_sizes[1] / 2;           // 1600000
    const int* src = ei;
    const int* dst = ei + e;
    const int nb = (n + 1023) >> 10;         // 98

    zero_kernel <<<(n + 255) / 256, 256>>>(n);
    cnt_kernel  <<<(e + 255) / 256, 256>>>(dst, e);
    scan1_kernel<<<nb, 1024>>>(n);
    scan2_kernel<<<1, 128>>>(nb);
    {
        int nGemm = (n + 127) / 128;
        int nFill = (e + 255) / 256;
        gemm1_fill_kernel<<<nGemm + nFill, 256>>>(x, Wc, src, dst, n, e, nGemm);
    }
    agg_gemm2_kernel<<<(n + 63) / 64, 256>>>(Wl, bc, bl, out, n);
}

// round 8
// speedup vs baseline: 1.0469x; 1.0469x over previous
#include <cuda_runtime.h>
#include <cuda_bf16.h>
#include <stdint.h>

#define N_NODES 100000
#define N_EDGES 1600000
#define IN_DIM  128
#define HID_DIM 64
#define OUT_DIM 128

// Scratch (allocation-free rule: __device__ globals)
__device__ __align__(16) float g_hs [(size_t)N_NODES * HID_DIM];   // (x@Wc)*dinv[row]
__device__ int g_cnt[N_NODES];
__device__ int g_off[N_NODES];   // global exclusive scan of cnt
__device__ int g_pos[N_NODES];
__device__ int g_bpub[128];      // packed (sum | FLAG) per scan block
__device__ int g_csr[N_EDGES];

#define PUB_FLAG 0x40000000

// ---------------------------------------------------------------- f32x2 helpers
__device__ __forceinline__ unsigned long long pack2(float x, float y) {
    unsigned long long r;
    asm("mov.b64 %0, {%1,%2};" : "=l"(r) : "f"(x), "f"(y));
    return r;
}
__device__ __forceinline__ float2 unpack2(unsigned long long v) {
    float2 r;
    asm("mov.b64 {%0,%1}, %2;" : "=f"(r.x), "=f"(r.y) : "l"(v));
    return r;
}
__device__ __forceinline__ void ffma2(unsigned long long& d, unsigned long long a,
                                      unsigned long long b) {
    asm("fma.rn.f32x2 %0, %1, %2, %0;" : "+l"(d) : "l"(a), "l"(b));
}
__device__ __forceinline__ unsigned long long mul2(unsigned long long a,
                                                   unsigned long long b) {
    unsigned long long d;
    asm("mul.rn.f32x2 %0, %1, %2;" : "=l"(d) : "l"(a), "l"(b));
    return d;
}
__device__ __forceinline__ unsigned long long add2(unsigned long long a,
                                                   unsigned long long b) {
    unsigned long long d;
    asm("add.rn.f32x2 %0, %1, %2;" : "=l"(d) : "l"(a), "l"(b));
    return d;
}

// ---------------------------------------------------------------- CSR build
__global__ void zero_kernel(int n) {
    int i = blockIdx.x * blockDim.x + threadIdx.x;
    if (i < n) g_cnt[i] = 0;
    if (i < 128) g_bpub[i] = 0;
}

// 4 edges per thread (int4)
__global__ void cnt_kernel(const int4* __restrict__ dst4, int e) {
    int i = blockIdx.x * blockDim.x + threadIdx.x;
    int e4 = e >> 2;
    if (i < e4) {
        int4 d = dst4[i];
        atomicAdd(&g_cnt[d.x], 1);
        atomicAdd(&g_cnt[d.y], 1);
        atomicAdd(&g_cnt[d.z], 1);
        atomicAdd(&g_cnt[d.w], 1);
    }
    if (i == 0) {
        const int* d1 = (const int*)dst4;
        for (int j = e4 * 4; j < e; j++) atomicAdd(&g_cnt[d1[j]], 1);
    }
}

// Single-pass exclusive scan (decoupled lookback; all blocks co-resident).
__global__ __launch_bounds__(1024) void scan_kernel(int n) {
    __shared__ int sh[1024];
    __shared__ int red[1024];
    const int t = threadIdx.x;
    const int b = blockIdx.x;
    const int i = b * 1024 + t;
    int v = (i < n) ? g_cnt[i] : 0;
    sh[t] = v;
    __syncthreads();
    #pragma unroll
    for (int d = 1; d < 1024; d <<= 1) {
        int u = (t >= d) ? sh[t - d] : 0;
        __syncthreads();
        sh[t] += u;
        __syncthreads();
    }
    int incl = sh[t];
    if (t == 1023) atomicExch(&g_bpub[b], incl | PUB_FLAG);

    // lookback: thread t spins on predecessor block t
    int pv = 0;
    if (t < b) {
        int w;
        do { w = atomicAdd(&g_bpub[t], 0); } while ((w & PUB_FLAG) == 0);
        pv = w & (PUB_FLAG - 1);
    }
    red[t] = pv;
    __syncthreads();
    #pragma unroll
    for (int s = 512; s > 0; s >>= 1) {
        if (t < s) red[t] += red[t + s];
        __syncthreads();
    }
    int prefix = red[0];
    if (i < n) { g_off[i] = prefix + incl - v; g_pos[i] = 0; }
}

// ---------------------------------------------------------------- GEMM1 + fill
// Blocks [0, nGemm): hs[r][c] = rsqrt(cnt[r]+1) * sum_k x[r][k]*Wc[k][c]
//   Tile M=128, N=64, K chunks of 32. 256 thr; warp tc owns 8 cols (broadcast W);
//   lane tr owns rows {tr, tr+32, tr+64, tr+96}.
// Blocks [nGemm, ...): CSR fill, 4 edges/thread (overlaps with the GEMM).
__global__ __launch_bounds__(256) void gemm1_fill_kernel(const float* __restrict__ x,
                                                         const float* __restrict__ Wc,
                                                         const int* __restrict__ src,
                                                         const int* __restrict__ dst,
                                                         int n, int e, int nGemm) {
    __shared__ float4 Xs[128 * 9];
    __shared__ float4 Ws[32 * 16];

    if (blockIdx.x >= nGemm) {   // ---- fill part
        int i = (blockIdx.x - nGemm) * 256 + threadIdx.x;
        int e4 = e >> 2;
        if (i < e4) {
            int4 s4 = ((const int4*)src)[i];
            int4 d4 = ((const int4*)dst)[i];
            int p;
            p = g_off[d4.x] + atomicAdd(&g_pos[d4.x], 1); g_csr[p] = s4.x;
            p = g_off[d4.y] + atomicAdd(&g_pos[d4.y], 1); g_csr[p] = s4.y;
            p = g_off[d4.z] + atomicAdd(&g_pos[d4.z], 1); g_csr[p] = s4.z;
            p = g_off[d4.w] + atomicAdd(&g_pos[d4.w], 1); g_csr[p] = s4.w;
        }
        if (i == 0) {
            for (int j = e4 * 4; j < e; j++) {
                int d = dst[j];
                int p = g_off[d] + atomicAdd(&g_pos[d], 1);
                g_csr[p] = src[j];
            }
        }
        return;
    }

    const int t = threadIdx.x;
    const int rowBase = blockIdx.x * 128;
    const int tr = t & 31;
    const int tc = t >> 5;

    unsigned long long acc[4][4];
    #pragma unroll
    for (int i = 0; i < 4; i++)
        #pragma unroll
        for (int c2 = 0; c2 < 4; c2++) acc[i][c2] = 0ull;

    const float4* Xg = (const float4*)x;
    const float4* Wg = (const float4*)Wc;

    for (int c = 0; c < 4; c++) {
        #pragma unroll
        for (int i = 0; i < 2; i++) {
            int idx = t + i * 256;
            int k = idx >> 4, col4 = idx & 15;
            Ws[idx] = Wg[(c * 32 + k) * 16 + col4];
        }
        #pragma unroll
        for (int i = 0; i < 4; i++) {
            int idx = t + i * 256;
            int r = idx >> 3, q = idx & 7;
            int row = rowBase + r;
            float4 v = make_float4(0.f, 0.f, 0.f, 0.f);
            if (row < n) v = Xg[(size_t)row * 32 + c * 8 + q];
            Xs[r * 9 + q] = v;
        }
        __syncthreads();

        #pragma unroll
        for (int kq = 0; kq < 8; kq++) {
            float4 xv[4];
            #pragma unroll
            for (int i = 0; i < 4; i++) xv[i] = Xs[(tr + 32 * i) * 9 + kq];
            #pragma unroll
            for (int kk = 0; kk < 4; kk++) {
                float4 w0 = Ws[(kq * 4 + kk) * 16 + tc * 2];
                float4 w1 = Ws[(kq * 4 + kk) * 16 + tc * 2 + 1];
                unsigned long long wp0 = pack2(w0.x, w0.y);
                unsigned long long wp1 = pack2(w0.z, w0.w);
                unsigned long long wp2 = pack2(w1.x, w1.y);
                unsigned long long wp3 = pack2(w1.z, w1.w);
                #pragma unroll
                for (int i = 0; i < 4; i++) {
                    float s = (kk == 0) ? xv[i].x : (kk == 1) ? xv[i].y
                            : (kk == 2) ? xv[i].z : xv[i].w;
                    unsigned long long ss = pack2(s, s);
                    ffma2(acc[i][0], ss, wp0);
                    ffma2(acc[i][1], ss, wp1);
                    ffma2(acc[i][2], ss, wp2);
                    ffma2(acc[i][3], ss, wp3);
                }
            }
        }
        __syncthreads();
    }

    #pragma unroll
    for (int i = 0; i < 4; i++) {
        int row = rowBase + tr + 32 * i;
        if (row < n) {
            float dv = rsqrtf((float)g_cnt[row] + 1.0f);
            unsigned long long dd = pack2(dv, dv);
            float2 a = unpack2(mul2(acc[i][0], dd));
            float2 b = unpack2(mul2(acc[i][1], dd));
            float2 cc = unpack2(mul2(acc[i][2], dd));
            float2 d = unpack2(mul2(acc[i][3], dd));
            size_t off = (size_t)row * 16 + tc * 2;
            ((float4*)g_hs)[off]     = make_float4(a.x, a.y, b.x, b.y);
            ((float4*)g_hs)[off + 1] = make_float4(cc.x, cc.y, d.x, d.y);
        }
    }
}

// ---------------------------------------------------------------- agg + GEMM2
// Block handles 64 rows. Phase 1: 16 groups of 16 threads aggregate 4 nodes each
// (self + CSR neighbors), apply dinv/bias/relu, write Hs. Phase 2: out = Hs@Wlin+blin.
__global__ __launch_bounds__(256) void agg_gemm2_kernel(const float* __restrict__ Wlin,
                                                        const float* __restrict__ bconv,
                                                        const float* __restrict__ blin,
                                                        float* __restrict__ out,
                                                        int n) {
    __shared__ float4 Hs[64 * 17];   // 64 rows x 16 float4 (+1 pad)
    __shared__ float4 Ws[32 * 32];   // 32 k x 128 cols
    const int t = threadIdx.x;
    const int rowBase = blockIdx.x * 64;
    const int tr = t & 31;
    const int tc = t >> 5;

    // ---- phase 1: aggregate
    {
        const int grp = t >> 4;      // 0..15
        const int c = t & 15;        // float4 chunk
        const float4* hs4 = (const float4*)g_hs;
        float4 bcv = __ldg((const float4*)&bconv[c * 4]);
        #pragma unroll
        for (int nn = 0; nn < 4; nn++) {
            int r = grp * 4 + nn;
            int node = rowBase + r;
            float4 res = make_float4(0.f, 0.f, 0.f, 0.f);
            if (node < n) {
                float4 a0 = hs4[(size_t)node * 16 + c];   // self-loop (pre-scaled)
                float4 a1 = make_float4(0.f, 0.f, 0.f, 0.f);
                float4 a2 = make_float4(0.f, 0.f, 0.f, 0.f);
                float4 a3 = make_float4(0.f, 0.f, 0.f, 0.f);
                int cnt = g_cnt[node];
                int beg = g_off[node];
                int end = beg + cnt;
                int j = beg;
                for (; j + 3 < end; j += 4) {
                    int s0 = g_csr[j],     s1 = g_csr[j + 1];
                    int s2 = g_csr[j + 2], s3 = g_csr[j + 3];
                    float4 v0 = hs4[(size_t)s0 * 16 + c];
                    float4 v1 = hs4[(size_t)s1 * 16 + c];
                    float4 v2 = hs4[(size_t)s2 * 16 + c];
                    float4 v3 = hs4[(size_t)s3 * 16 + c];
                    a0.x += v0.x; a0.y += v0.y; a0.z += v0.z; a0.w += v0.w;
                    a1.x += v1.x; a1.y += v1.y; a1.z += v1.z; a1.w += v1.w;
                    a2.x += v2.x; a2.y += v2.y; a2.z += v2.z; a2.w += v2.w;
                    a3.x += v3.x; a3.y += v3.y; a3.z += v3.z; a3.w += v3.w;
                }
                for (; j < end; j++) {
                    int s0 = g_csr[j];
                    float4 v0 = hs4[(size_t)s0 * 16 + c];
                    a0.x += v0.x; a0.y += v0.y; a0.z += v0.z; a0.w += v0.w;
                }
                a0.x += a1.x + a2.x + a3.x;
                a0.y += a1.y + a2.y + a3.y;
                a0.z += a1.z + a2.z + a3.z;
                a0.w += a1.w + a2.w + a3.w;
                float dv = rsqrtf((float)cnt + 1.0f);
                res.x = fmaxf(fmaf(a0.x, dv, bcv.x), 0.f);
                res.y = fmaxf(fmaf(a0.y, dv, bcv.y), 0.f);
                res.z = fmaxf(fmaf(a0.z, dv, bcv.z), 0.f);
                res.w = fmaxf(fmaf(a0.w, dv, bcv.w), 0.f);
            }
            Hs[r * 17 + c] = res;
        }
    }

    // ---- phase 2: GEMM, K=64 in 2 chunks of 32 (Ws reuse)
    unsigned long long acc[2][8];
    #pragma unroll
    for (int i = 0; i < 2; i++)
        #pragma unroll
        for (int c2 = 0; c2 < 8; c2++) acc[i][c2] = 0ull;

    const float4* Wg = (const float4*)Wlin;

    for (int c = 0; c < 2; c++) {
        __syncthreads();   // Hs ready (c==0) / Ws drained (c==1)
        #pragma unroll
        for (int i = 0; i < 4; i++) {
            int idx = t + i * 256;
            int k = idx >> 5, col4 = idx & 31;
            Ws[idx] = Wg[(c * 32 + k) * 32 + col4];
        }
        __syncthreads();

        #pragma unroll
        for (int kq = 0; kq < 8; kq++) {
            float4 xv[2];
            #pragma unroll
            for (int i = 0; i < 2; i++) xv[i] = Hs[(tr + 32 * i) * 17 + c * 8 + kq];
            #pragma unroll
            for (int kk = 0; kk < 4; kk++) {
                unsigned long long wp[8];
                #pragma unroll
                for (int m = 0; m < 4; m++) {
                    float4 w = Ws[(kq * 4 + kk) * 32 + tc * 4 + m];
                    wp[m * 2]     = pack2(w.x, w.y);
                    wp[m * 2 + 1] = pack2(w.z, w.w);
                }
                #pragma unroll
                for (int i = 0; i < 2; i++) {
                    float s = (kk == 0) ? xv[i].x : (kk == 1) ? xv[i].y
                            : (kk == 2) ? xv[i].z : xv[i].w;
                    unsigned long long ss = pack2(s, s);
                    #pragma unroll
                    for (int c2 = 0; c2 < 8; c2++) ffma2(acc[i][c2], ss, wp[c2]);
                }
            }
        }
    }

    unsigned long long blp[8];
    #pragma unroll
    for (int m = 0; m < 4; m++) {
        float4 b = __ldg((const float4*)&blin[tc * 16 + m * 4]);
        blp[m * 2]     = pack2(b.x, b.y);
        blp[m * 2 + 1] = pack2(b.z, b.w);
    }
    #pragma unroll
    for (int i = 0; i < 2; i++) {
        int row = rowBase + tr + 32 * i;
        if (row < n) {
            size_t off = (size_t)row * 32 + tc * 4;
            #pragma unroll
            for (int m = 0; m < 4; m++) {
                float2 lo = unpack2(add2(acc[i][m * 2],     blp[m * 2]));
                float2 hi = unpack2(add2(acc[i][m * 2 + 1], blp[m * 2 + 1]));
                ((float4*)out)[off + m] = make_float4(lo.x, lo.y, hi.x, hi.y);
            }
        }
    }
}

// ---------------------------------------------------------------- launch
extern "C" void kernel_launch(void* const* d_in, const int* in_sizes, int n_in,
                              void* d_out, int out_size) {
    const float* x  = (const float*)d_in[0];
    const int*   ei = (const int*)  d_in[1];
    const float* Wc = (const float*)d_in[2];
    const float* bc = (const float*)d_in[3];
    const float* Wl = (const float*)d_in[4];
    const float* bl = (const float*)d_in[5];
    float*       out = (float*)d_out;

    const int n = in_sizes[0] / IN_DIM;      // 100000
    const int e = in_sizes[1] / 2;           // 1600000
    const int* src = ei;
    const int* dst = ei + e;
    const int nb = (n + 1023) >> 10;         // 98 (must be <= 128)

    zero_kernel<<<(n + 255) / 256, 256>>>(n);
    cnt_kernel <<<((e >> 2) + 255) / 256, 256>>>((const int4*)dst, e);
    scan_kernel<<<nb, 1024>>>(n);
    {
        int nGemm = (n + 127) / 128;
        int nFill = ((e >> 2) + 255) / 256;
        gemm1_fill_kernel<<<nGemm + nFill, 256>>>(x, Wc, src, dst, n, e, nGemm);
    }
    agg_gemm2_kernel<<<(n + 63) / 64, 256>>>(Wl, bc, bl, out, n);
}